// round 2
// baseline (speedup 1.0000x reference)
#include <cuda_runtime.h>
#include <cuda_bf16.h>

#define N_NODES 50000
#define N_EDGES 800000
#define D_MODEL 128
#define N_HEADS 8
#define D_HEAD  16

// ---------------- scratch (static device globals; no allocs allowed) --------
__device__ __align__(16) float    g_h[N_NODES * D_MODEL];          // layernormed x
__device__ __align__(16) float    g_qkv[N_NODES * 3 * D_MODEL];    // [node][q k v]
__device__ __align__(16) float    g_e[N_EDGES * N_HEADS];          // scores -> exp
__device__ __align__(16) unsigned g_mkey[N_NODES * N_HEADS];       // segment max keys
__device__ __align__(16) float    g_s[N_NODES * N_HEADS];          // segment sums
__device__ __align__(16) float    g_agg[N_NODES * D_MODEL];        // aggregated msgs

// ---------------- init: zero / sentinel the accumulators --------------------
__global__ void k_init() {
    int i = blockIdx.x * blockDim.x + threadIdx.x;
    if (i < N_NODES * D_MODEL) g_agg[i] = 0.f;
    if (i < N_NODES * N_HEADS) { g_s[i] = 0.f; g_mkey[i] = 0u; }
}

// ---------------- layernorm: one warp per node ------------------------------
__global__ void k_ln(const float* __restrict__ x,
                     const float* __restrict__ lg,
                     const float* __restrict__ lb) {
    int warp = (blockIdx.x * blockDim.x + threadIdx.x) >> 5;
    int lane = threadIdx.x & 31;
    if (warp >= N_NODES) return;
    float4 v = *(const float4*)&x[warp * D_MODEL + lane * 4];
    float s  = v.x + v.y + v.z + v.w;
    float ss = v.x*v.x + v.y*v.y + v.z*v.z + v.w*v.w;
    #pragma unroll
    for (int o = 16; o; o >>= 1) {
        s  += __shfl_xor_sync(0xFFFFFFFFu, s,  o);
        ss += __shfl_xor_sync(0xFFFFFFFFu, ss, o);
    }
    float mu  = s  * (1.0f / D_MODEL);
    float var = ss * (1.0f / D_MODEL) - mu * mu;
    float inv = rsqrtf(var + 1e-5f);
    float4 gg = *(const float4*)&lg[lane * 4];
    float4 bb = *(const float4*)&lb[lane * 4];
    float4 o;
    o.x = (v.x - mu) * inv * gg.x + bb.x;
    o.y = (v.y - mu) * inv * gg.y + bb.y;
    o.z = (v.z - mu) * inv * gg.z + bb.z;
    o.w = (v.w - mu) * inv * gg.w + bb.w;
    *(float4*)&g_h[warp * D_MODEL + lane * 4] = o;
}

// ---------------- QKV GEMM: h(N,128) @ w(128,384) + b -----------------------
__global__ void k_qkv(const float* __restrict__ w, const float* __restrict__ b) {
    __shared__ float sh[64][33];
    __shared__ float sw[32][128];
    int bm = blockIdx.x, bn = blockIdx.y;
    int tid  = threadIdx.x;
    int colg = tid & 31;
    int rowg = tid >> 5;
    int c0 = bn * 128 + colg * 4;
    float acc[8][4];
    #pragma unroll
    for (int i = 0; i < 8; i++) { acc[i][0]=0.f; acc[i][1]=0.f; acc[i][2]=0.f; acc[i][3]=0.f; }

    for (int k0 = 0; k0 < D_MODEL; k0 += 32) {
        for (int i = tid; i < 64 * 8; i += 256) {
            int r = i >> 3, cc = (i & 7) * 4;
            int gr = min(bm * 64 + r, N_NODES - 1);
            float4 v = *(const float4*)&g_h[gr * D_MODEL + k0 + cc];
            sh[r][cc] = v.x; sh[r][cc+1] = v.y; sh[r][cc+2] = v.z; sh[r][cc+3] = v.w;
        }
        for (int i = tid; i < 32 * 32; i += 256) {
            int r = i >> 5, cc = (i & 31) * 4;
            float4 v = *(const float4*)&w[(k0 + r) * 384 + bn * 128 + cc];
            *(float4*)&sw[r][cc] = v;
        }
        __syncthreads();
        #pragma unroll
        for (int kk = 0; kk < 32; kk++) {
            float4 wv = *(float4*)&sw[kk][colg * 4];
            #pragma unroll
            for (int i = 0; i < 8; i++) {
                float hv = sh[rowg * 8 + i][kk];
                acc[i][0] += hv * wv.x;
                acc[i][1] += hv * wv.y;
                acc[i][2] += hv * wv.z;
                acc[i][3] += hv * wv.w;
            }
        }
        __syncthreads();
    }
    float4 bias = *(const float4*)&b[c0];
    #pragma unroll
    for (int i = 0; i < 8; i++) {
        int node = bm * 64 + rowg * 8 + i;
        if (node < N_NODES) {
            float4 o;
            o.x = acc[i][0] + bias.x; o.y = acc[i][1] + bias.y;
            o.z = acc[i][2] + bias.z; o.w = acc[i][3] + bias.w;
            *(float4*)&g_qkv[node * 384 + c0] = o;
        }
    }
}

// ---------------- edge pass 1: scores + segment max (warp per edge) ---------
__global__ void k_edge1(const float* __restrict__ ea, const int* __restrict__ ei) {
    int gw = (blockIdx.x * blockDim.x + threadIdx.x) >> 5;
    if (gw >= N_EDGES) return;
    int lane = threadIdx.x & 31;
    int src = ei[gw];
    int dst = ei[N_EDGES + gw];
    float4 qv = *(const float4*)&g_qkv[dst * 384 + lane * 4];
    float4 kv = *(const float4*)&g_qkv[src * 384 + 128 + lane * 4];
    float4 av = *(const float4*)&ea[(long long)gw * D_MODEL + lane * 4];
    float p = qv.x * (kv.x + av.x) + qv.y * (kv.y + av.y)
            + qv.z * (kv.z + av.z) + qv.w * (kv.w + av.w);
    p += __shfl_xor_sync(0xFFFFFFFFu, p, 1);
    p += __shfl_xor_sync(0xFFFFFFFFu, p, 2);
    if ((lane & 3) == 0) {
        int hh = lane >> 2;
        float score = p * 0.25f;   // DH^-0.5 = 1/4
        g_e[gw * N_HEADS + hh] = score;
        unsigned u = __float_as_uint(score);
        unsigned key = (u & 0x80000000u) ? ~u : (u | 0x80000000u);
        atomicMax(&g_mkey[dst * N_HEADS + hh], key);
    }
}

// ---------------- edge pass 2: exp + segment sum (thread per edge-head) -----
__global__ void k_edge2(const int* __restrict__ ei) {
    int i = blockIdx.x * blockDim.x + threadIdx.x;
    if (i >= N_EDGES * N_HEADS) return;
    int e  = i >> 3;
    int hh = i & 7;
    int dst = ei[N_EDGES + e];
    unsigned key = g_mkey[dst * N_HEADS + hh];
    float m;
    if (key == 0u) m = 0.f;
    else {
        unsigned u = (key & 0x80000000u) ? (key ^ 0x80000000u) : ~key;
        m = __uint_as_float(u);
    }
    float ex = __expf(g_e[i] - m);
    g_e[i] = ex;
    atomicAdd(&g_s[dst * N_HEADS + hh], ex);
}

// ---------------- edge pass 3: weighted V scatter-add (warp per edge) -------
__global__ void k_edge3(const int* __restrict__ ei) {
    int gw = (blockIdx.x * blockDim.x + threadIdx.x) >> 5;
    if (gw >= N_EDGES) return;
    int lane = threadIdx.x & 31;
    int src = ei[gw];
    int dst = ei[N_EDGES + gw];
    int hh = lane >> 2;
    float ev = g_e[gw * N_HEADS + hh];
    float sv = g_s[dst * N_HEADS + hh];
    float a = ev / fmaxf(sv, 1e-16f);
    float4 vv = *(const float4*)&g_qkv[src * 384 + 256 + lane * 4];
    float* dp = &g_agg[dst * D_MODEL + lane * 4];
    asm volatile("red.global.add.v4.f32 [%0], {%1, %2, %3, %4};"
                 :: "l"(dp), "f"(vv.x * a), "f"(vv.y * a), "f"(vv.z * a), "f"(vv.w * a)
                 : "memory");
}

// ---------------- out GEMM: agg(N,128) @ out_w(128,128) + b + x -------------
__global__ void k_out(const float* __restrict__ w, const float* __restrict__ b,
                      const float* __restrict__ x, float* __restrict__ out) {
    __shared__ float sh[64][33];
    __shared__ float sw[32][128];
    int bm = blockIdx.x;
    int tid  = threadIdx.x;
    int colg = tid & 31;
    int rowg = tid >> 5;
    int c0 = colg * 4;
    float acc[8][4];
    #pragma unroll
    for (int i = 0; i < 8; i++) { acc[i][0]=0.f; acc[i][1]=0.f; acc[i][2]=0.f; acc[i][3]=0.f; }

    for (int k0 = 0; k0 < D_MODEL; k0 += 32) {
        for (int i = tid; i < 64 * 8; i += 256) {
            int r = i >> 3, cc = (i & 7) * 4;
            int gr = min(bm * 64 + r, N_NODES - 1);
            float4 v = *(const float4*)&g_agg[gr * D_MODEL + k0 + cc];
            sh[r][cc] = v.x; sh[r][cc+1] = v.y; sh[r][cc+2] = v.z; sh[r][cc+3] = v.w;
        }
        for (int i = tid; i < 32 * 32; i += 256) {
            int r = i >> 5, cc = (i & 31) * 4;
            float4 v = *(const float4*)&w[(k0 + r) * D_MODEL + cc];
            *(float4*)&sw[r][cc] = v;
        }
        __syncthreads();
        #pragma unroll
        for (int kk = 0; kk < 32; kk++) {
            float4 wv = *(float4*)&sw[kk][colg * 4];
            #pragma unroll
            for (int i = 0; i < 8; i++) {
                float hv = sh[rowg * 8 + i][kk];
                acc[i][0] += hv * wv.x;
                acc[i][1] += hv * wv.y;
                acc[i][2] += hv * wv.z;
                acc[i][3] += hv * wv.w;
            }
        }
        __syncthreads();
    }
    float4 bias = *(const float4*)&b[c0];
    #pragma unroll
    for (int i = 0; i < 8; i++) {
        int node = bm * 64 + rowg * 8 + i;
        if (node < N_NODES) {
            float4 xr = *(const float4*)&x[node * D_MODEL + c0];
            float4 o;
            o.x = acc[i][0] + bias.x + xr.x;
            o.y = acc[i][1] + bias.y + xr.y;
            o.z = acc[i][2] + bias.z + xr.z;
            o.w = acc[i][3] + bias.w + xr.w;
            *(float4*)&out[node * D_MODEL + c0] = o;
        }
    }
}

// ---------------- launch -----------------------------------------------------
extern "C" void kernel_launch(void* const* d_in, const int* in_sizes, int n_in,
                              void* d_out, int out_size) {
    const float* x     = (const float*)d_in[0];
    const float* ea    = (const float*)d_in[1];
    const float* qkv_w = (const float*)d_in[2];
    const float* qkv_b = (const float*)d_in[3];
    const float* out_w = (const float*)d_in[4];
    const float* out_b = (const float*)d_in[5];
    const float* ln_g  = (const float*)d_in[6];
    const float* ln_b  = (const float*)d_in[7];
    const int*   ei    = (const int*)d_in[8];   // JAX x64 disabled -> int32 [2, E]
    float* out = (float*)d_out;

    k_init<<<(N_NODES * D_MODEL + 255) / 256, 256>>>();
    k_ln<<<(N_NODES + 7) / 8, 256>>>(x, ln_g, ln_b);

    dim3 gq((N_NODES + 63) / 64, 3);
    k_qkv<<<gq, 256>>>(qkv_w, qkv_b);

    k_edge1<<<(N_EDGES + 7) / 8, 256>>>(ea, ei);
    k_edge2<<<(N_EDGES * N_HEADS + 255) / 256, 256>>>(ei);
    k_edge3<<<(N_EDGES + 7) / 8, 256>>>(ei);

    k_out<<<(N_NODES + 63) / 64, 256>>>(out_w, out_b, x, out);
}

// round 3
// speedup vs baseline: 1.0529x; 1.0529x over previous
#include <cuda_runtime.h>
#include <cuda_bf16.h>
#include <math_constants.h>

#define N_NODES 50000
#define N_EDGES 800000
#define D_MODEL 128
#define N_HEADS 8
#define D_HEAD  16

// ---------------- scratch (static device globals; no allocs allowed) --------
__device__ __align__(16) float g_h[N_NODES * D_MODEL];        // layernormed x
__device__ __align__(16) float g_qkv[N_NODES * 3 * D_MODEL];  // [node][q k v]
__device__ __align__(16) float g_e[(size_t)N_EDGES * N_HEADS];// scores (CSR order)
__device__ __align__(16) float g_agg[N_NODES * D_MODEL];      // aggregated msgs
__device__ int g_cnt[N_NODES];          // histogram
__device__ int g_off[N_NODES + 1];      // CSR offsets
__device__ int g_cursor[N_NODES];       // scatter cursors
__device__ int g_csr_src[N_EDGES];      // src node per CSR slot
__device__ int g_csr_eid[N_EDGES];      // original edge id per CSR slot

// ---------------- CSR build --------------------------------------------------
__global__ void k_zero_cnt() {
    int i = blockIdx.x * blockDim.x + threadIdx.x;
    if (i < N_NODES) g_cnt[i] = 0;
}

__global__ void k_hist(const int* __restrict__ ei) {
    int i = blockIdx.x * blockDim.x + threadIdx.x;
    if (i < N_EDGES) atomicAdd(&g_cnt[ei[N_EDGES + i]], 1);
}

// single block, 1024 threads: chunked exclusive scan of g_cnt -> g_off, cursors
__global__ void k_scan() {
    __shared__ int part[1024];
    int t = threadIdx.x;
    const int CH = (N_NODES + 1023) / 1024;   // 49
    int base = t * CH;
    int s = 0;
    for (int i = 0; i < CH; i++) {
        int idx = base + i;
        if (idx < N_NODES) s += g_cnt[idx];
    }
    part[t] = s;
    __syncthreads();
    // Hillis-Steele inclusive scan
    for (int o = 1; o < 1024; o <<= 1) {
        int u = (t >= o) ? part[t - o] : 0;
        __syncthreads();
        part[t] += u;
        __syncthreads();
    }
    int run = part[t] - s;   // exclusive prefix for this chunk
    for (int i = 0; i < CH; i++) {
        int idx = base + i;
        if (idx < N_NODES) {
            int c = g_cnt[idx];
            g_off[idx] = run;
            g_cursor[idx] = run;
            run += c;
        }
    }
    if (t == 1023) g_off[N_NODES] = N_EDGES;
}

__global__ void k_scatter(const int* __restrict__ ei) {
    int i = blockIdx.x * blockDim.x + threadIdx.x;
    if (i >= N_EDGES) return;
    int dst = ei[N_EDGES + i];
    int pos = atomicAdd(&g_cursor[dst], 1);
    g_csr_src[pos] = ei[i];
    g_csr_eid[pos] = i;
}

// ---------------- layernorm: one warp per node ------------------------------
__global__ void k_ln(const float* __restrict__ x,
                     const float* __restrict__ lg,
                     const float* __restrict__ lb) {
    int warp = (blockIdx.x * blockDim.x + threadIdx.x) >> 5;
    int lane = threadIdx.x & 31;
    if (warp >= N_NODES) return;
    float4 v = *(const float4*)&x[warp * D_MODEL + lane * 4];
    float s  = v.x + v.y + v.z + v.w;
    float ss = v.x*v.x + v.y*v.y + v.z*v.z + v.w*v.w;
    #pragma unroll
    for (int o = 16; o; o >>= 1) {
        s  += __shfl_xor_sync(0xFFFFFFFFu, s,  o);
        ss += __shfl_xor_sync(0xFFFFFFFFu, ss, o);
    }
    float mu  = s  * (1.0f / D_MODEL);
    float var = ss * (1.0f / D_MODEL) - mu * mu;
    float inv = rsqrtf(var + 1e-5f);
    float4 gg = *(const float4*)&lg[lane * 4];
    float4 bb = *(const float4*)&lb[lane * 4];
    float4 o;
    o.x = (v.x - mu) * inv * gg.x + bb.x;
    o.y = (v.y - mu) * inv * gg.y + bb.y;
    o.z = (v.z - mu) * inv * gg.z + bb.z;
    o.w = (v.w - mu) * inv * gg.w + bb.w;
    *(float4*)&g_h[warp * D_MODEL + lane * 4] = o;
}

// ---------------- QKV GEMM: h(N,128) @ w(128,384) + b -----------------------
__global__ void k_qkv(const float* __restrict__ w, const float* __restrict__ b) {
    __shared__ float sh[64][33];
    __shared__ float sw[32][128];
    int bm = blockIdx.x, bn = blockIdx.y;
    int tid  = threadIdx.x;
    int colg = tid & 31;
    int rowg = tid >> 5;
    int c0 = bn * 128 + colg * 4;
    float acc[8][4];
    #pragma unroll
    for (int i = 0; i < 8; i++) { acc[i][0]=0.f; acc[i][1]=0.f; acc[i][2]=0.f; acc[i][3]=0.f; }

    for (int k0 = 0; k0 < D_MODEL; k0 += 32) {
        for (int i = tid; i < 64 * 8; i += 256) {
            int r = i >> 3, cc = (i & 7) * 4;
            int gr = min(bm * 64 + r, N_NODES - 1);
            float4 v = *(const float4*)&g_h[gr * D_MODEL + k0 + cc];
            sh[r][cc] = v.x; sh[r][cc+1] = v.y; sh[r][cc+2] = v.z; sh[r][cc+3] = v.w;
        }
        for (int i = tid; i < 32 * 32; i += 256) {
            int r = i >> 5, cc = (i & 31) * 4;
            float4 v = *(const float4*)&w[(k0 + r) * 384 + bn * 128 + cc];
            *(float4*)&sw[r][cc] = v;
        }
        __syncthreads();
        #pragma unroll
        for (int kk = 0; kk < 32; kk++) {
            float4 wv = *(float4*)&sw[kk][colg * 4];
            #pragma unroll
            for (int i = 0; i < 8; i++) {
                float hv = sh[rowg * 8 + i][kk];
                acc[i][0] += hv * wv.x;
                acc[i][1] += hv * wv.y;
                acc[i][2] += hv * wv.z;
                acc[i][3] += hv * wv.w;
            }
        }
        __syncthreads();
    }
    float4 bias = *(const float4*)&b[c0];
    #pragma unroll
    for (int i = 0; i < 8; i++) {
        int node = bm * 64 + rowg * 8 + i;
        if (node < N_NODES) {
            float4 o;
            o.x = acc[i][0] + bias.x; o.y = acc[i][1] + bias.y;
            o.z = acc[i][2] + bias.z; o.w = acc[i][3] + bias.w;
            *(float4*)&g_qkv[node * 384 + c0] = o;
        }
    }
}

// ---------------- fused edge phase: warp per dst node, no atomics -----------
__global__ void k_edge_fused(const float* __restrict__ ea) {
    int node = (blockIdx.x * blockDim.x + threadIdx.x) >> 5;
    if (node >= N_NODES) return;
    int lane = threadIdx.x & 31;
    int h = lane >> 2;
    int beg = g_off[node], end = g_off[node + 1];

    float4 q4 = *(const float4*)&g_qkv[node * 384 + lane * 4];

    // pass 1: scores + per-head max (scores parked in g_e, CSR order)
    float m = -CUDART_INF_F;
    for (int e = beg; e < end; e++) {
        int src = g_csr_src[e];
        int eid = g_csr_eid[e];
        float4 kv = *(const float4*)&g_qkv[src * 384 + 128 + lane * 4];
        float4 av = *(const float4*)&ea[(size_t)eid * D_MODEL + lane * 4];
        float p = q4.x * (kv.x + av.x) + q4.y * (kv.y + av.y)
                + q4.z * (kv.z + av.z) + q4.w * (kv.w + av.w);
        p += __shfl_xor_sync(0xFFFFFFFFu, p, 1);
        p += __shfl_xor_sync(0xFFFFFFFFu, p, 2);   // all 4 lanes of group hold sum
        p *= 0.25f;                                 // DH^-0.5
        m = fmaxf(m, p);
        if ((lane & 3) == 0) g_e[(size_t)e * N_HEADS + h] = p;
    }
    // m identical across the 4 lanes of each head group.

    // pass 2: softmax-linearity — unnormalized accumulate, divide at end
    float S = 0.f;
    float ax = 0.f, ay = 0.f, az = 0.f, aw = 0.f;
    for (int e = beg; e < end; e++) {
        int src = g_csr_src[e];
        float sc = g_e[(size_t)e * N_HEADS + h];   // broadcast within group
        float ex = __expf(sc - m);
        S += ex;
        float4 vv = *(const float4*)&g_qkv[src * 384 + 256 + lane * 4];
        ax += ex * vv.x; ay += ex * vv.y; az += ex * vv.z; aw += ex * vv.w;
    }
    float r = 1.f / fmaxf(S, 1e-16f);
    float4 o; o.x = ax * r; o.y = ay * r; o.z = az * r; o.w = aw * r;
    if (beg == end) { o.x = 0.f; o.y = 0.f; o.z = 0.f; o.w = 0.f; }
    *(float4*)&g_agg[node * D_MODEL + lane * 4] = o;
}

// ---------------- out GEMM: agg(N,128) @ out_w(128,128) + b + x -------------
__global__ void k_out(const float* __restrict__ w, const float* __restrict__ b,
                      const float* __restrict__ x, float* __restrict__ out) {
    __shared__ float sh[64][33];
    __shared__ float sw[32][128];
    int bm = blockIdx.x;
    int tid  = threadIdx.x;
    int colg = tid & 31;
    int rowg = tid >> 5;
    int c0 = colg * 4;
    float acc[8][4];
    #pragma unroll
    for (int i = 0; i < 8; i++) { acc[i][0]=0.f; acc[i][1]=0.f; acc[i][2]=0.f; acc[i][3]=0.f; }

    for (int k0 = 0; k0 < D_MODEL; k0 += 32) {
        for (int i = tid; i < 64 * 8; i += 256) {
            int r = i >> 3, cc = (i & 7) * 4;
            int gr = min(bm * 64 + r, N_NODES - 1);
            float4 v = *(const float4*)&g_agg[gr * D_MODEL + k0 + cc];
            sh[r][cc] = v.x; sh[r][cc+1] = v.y; sh[r][cc+2] = v.z; sh[r][cc+3] = v.w;
        }
        for (int i = tid; i < 32 * 32; i += 256) {
            int r = i >> 5, cc = (i & 31) * 4;
            float4 v = *(const float4*)&w[(k0 + r) * D_MODEL + cc];
            *(float4*)&sw[r][cc] = v;
        }
        __syncthreads();
        #pragma unroll
        for (int kk = 0; kk < 32; kk++) {
            float4 wv = *(float4*)&sw[kk][colg * 4];
            #pragma unroll
            for (int i = 0; i < 8; i++) {
                float hv = sh[rowg * 8 + i][kk];
                acc[i][0] += hv * wv.x;
                acc[i][1] += hv * wv.y;
                acc[i][2] += hv * wv.z;
                acc[i][3] += hv * wv.w;
            }
        }
        __syncthreads();
    }
    float4 bias = *(const float4*)&b[c0];
    #pragma unroll
    for (int i = 0; i < 8; i++) {
        int node = bm * 64 + rowg * 8 + i;
        if (node < N_NODES) {
            float4 xr = *(const float4*)&x[node * D_MODEL + c0];
            float4 o;
            o.x = acc[i][0] + bias.x + xr.x;
            o.y = acc[i][1] + bias.y + xr.y;
            o.z = acc[i][2] + bias.z + xr.z;
            o.w = acc[i][3] + bias.w + xr.w;
            *(float4*)&out[node * D_MODEL + c0] = o;
        }
    }
}

// ---------------- launch -----------------------------------------------------
extern "C" void kernel_launch(void* const* d_in, const int* in_sizes, int n_in,
                              void* d_out, int out_size) {
    const float* x     = (const float*)d_in[0];
    const float* ea    = (const float*)d_in[1];
    const float* qkv_w = (const float*)d_in[2];
    const float* qkv_b = (const float*)d_in[3];
    const float* out_w = (const float*)d_in[4];
    const float* out_b = (const float*)d_in[5];
    const float* ln_g  = (const float*)d_in[6];
    const float* ln_b  = (const float*)d_in[7];
    const int*   ei    = (const int*)d_in[8];   // int32 [2, E]: src row, dst row
    float* out = (float*)d_out;

    // CSR build
    k_zero_cnt<<<(N_NODES + 255) / 256, 256>>>();
    k_hist<<<(N_EDGES + 255) / 256, 256>>>(ei);
    k_scan<<<1, 1024>>>();
    k_scatter<<<(N_EDGES + 255) / 256, 256>>>(ei);

    // node pipeline
    k_ln<<<(N_NODES + 7) / 8, 256>>>(x, ln_g, ln_b);
    dim3 gq((N_NODES + 63) / 64, 3);
    k_qkv<<<gq, 256>>>(qkv_w, qkv_b);

    // fused edge phase: 1 warp per node
    k_edge_fused<<<(N_NODES + 7) / 8, 256>>>(ea);

    // output gemm + bias + residual
    k_out<<<(N_NODES + 63) / 64, 256>>>(out_w, out_b, x, out);
}

// round 5
// speedup vs baseline: 1.0558x; 1.0027x over previous
#include <cuda_runtime.h>
#include <cuda_bf16.h>
#include <math_constants.h>

#define N_NODES 50000
#define N_EDGES 800000
#define D_MODEL 128
#define N_HEADS 8
#define D_HEAD  16

// ---------------- scratch (static device globals) ---------------------------
__device__ __align__(16) float g_h[N_NODES * D_MODEL];
__device__ __align__(16) float g_qkv[N_NODES * 3 * D_MODEL];
__device__ __align__(16) float g_agg[N_NODES * D_MODEL];
__device__ int g_cnt[N_NODES];
__device__ int g_off[N_NODES + 1];
__device__ int g_cursor[N_NODES];
__device__ int g_csr_src[N_EDGES];
__device__ int g_csr_eid[N_EDGES];

// ---------------- CSR build --------------------------------------------------
__global__ void k_zero_cnt() {
    int i = blockIdx.x * blockDim.x + threadIdx.x;
    if (i < N_NODES) g_cnt[i] = 0;
}

__global__ void k_hist(const int* __restrict__ ei) {
    int i = blockIdx.x * blockDim.x + threadIdx.x;
    if (i < N_EDGES) atomicAdd(&g_cnt[ei[N_EDGES + i]], 1);
}

__global__ void k_scan() {
    __shared__ int part[1024];
    int t = threadIdx.x;
    const int CH = (N_NODES + 1023) / 1024;
    int base = t * CH;
    int s = 0;
    for (int i = 0; i < CH; i++) {
        int idx = base + i;
        if (idx < N_NODES) s += g_cnt[idx];
    }
    part[t] = s;
    __syncthreads();
    for (int o = 1; o < 1024; o <<= 1) {
        int u = (t >= o) ? part[t - o] : 0;
        __syncthreads();
        part[t] += u;
        __syncthreads();
    }
    int run = part[t] - s;
    for (int i = 0; i < CH; i++) {
        int idx = base + i;
        if (idx < N_NODES) {
            int c = g_cnt[idx];
            g_off[idx] = run;
            g_cursor[idx] = run;
            run += c;
        }
    }
    if (t == 1023) g_off[N_NODES] = N_EDGES;
}

__global__ void k_scatter(const int* __restrict__ ei) {
    int i = blockIdx.x * blockDim.x + threadIdx.x;
    if (i >= N_EDGES) return;
    int dst = ei[N_EDGES + i];
    int pos = atomicAdd(&g_cursor[dst], 1);
    g_csr_src[pos] = ei[i];
    g_csr_eid[pos] = i;
}

// ---------------- layernorm --------------------------------------------------
__global__ void k_ln(const float* __restrict__ x,
                     const float* __restrict__ lg,
                     const float* __restrict__ lb) {
    int warp = (blockIdx.x * blockDim.x + threadIdx.x) >> 5;
    int lane = threadIdx.x & 31;
    if (warp >= N_NODES) return;
    float4 v = *(const float4*)&x[warp * D_MODEL + lane * 4];
    float s  = v.x + v.y + v.z + v.w;
    float ss = v.x*v.x + v.y*v.y + v.z*v.z + v.w*v.w;
    #pragma unroll
    for (int o = 16; o; o >>= 1) {
        s  += __shfl_xor_sync(0xFFFFFFFFu, s,  o);
        ss += __shfl_xor_sync(0xFFFFFFFFu, ss, o);
    }
    float mu  = s  * (1.0f / D_MODEL);
    float var = ss * (1.0f / D_MODEL) - mu * mu;
    float inv = rsqrtf(var + 1e-5f);
    float4 gg = *(const float4*)&lg[lane * 4];
    float4 bb = *(const float4*)&lb[lane * 4];
    float4 o;
    o.x = (v.x - mu) * inv * gg.x + bb.x;
    o.y = (v.y - mu) * inv * gg.y + bb.y;
    o.z = (v.z - mu) * inv * gg.z + bb.z;
    o.w = (v.w - mu) * inv * gg.w + bb.w;
    *(float4*)&g_h[warp * D_MODEL + lane * 4] = o;
}

// ---------------- tf32 helpers -----------------------------------------------
__device__ __forceinline__ unsigned f2tf32(float f) {
    unsigned r;
    asm("cvt.rna.tf32.f32 %0, %1;" : "=r"(r) : "f"(f));
    return r;
}

__device__ __forceinline__ void mma_tf32(float* d, const unsigned* a, const unsigned* b) {
    asm volatile(
        "mma.sync.aligned.m16n8k8.row.col.f32.tf32.tf32.f32 "
        "{%0,%1,%2,%3}, {%4,%5,%6,%7}, {%8,%9}, {%0,%1,%2,%3};"
        : "+f"(d[0]), "+f"(d[1]), "+f"(d[2]), "+f"(d[3])
        : "r"(a[0]), "r"(a[1]), "r"(a[2]), "r"(a[3]), "r"(b[0]), "r"(b[1]));
}

// ---------------- 3xTF32 GEMM ------------------------------------------------
// SEL=0: A=g_h (N,128) @ w(128,384)+b -> g_qkv (stride 384)
// SEL=1: A=g_agg (N,128) @ w(128,128)+b + x -> outparam (stride 128)
// Block tile 128x128, 8 warps (32x64 warp tile), K-slice 32.
template<int SEL>
__global__ void k_gemm_tc(const float* __restrict__ w, const float* __restrict__ b,
                          const float* __restrict__ x, float* __restrict__ outparam) {
    constexpr int WSTRIDE = (SEL == 0) ? 384 : 128;
    constexpr int OSTRIDE = (SEL == 0) ? 384 : 128;
    const float* a_src = (SEL == 0) ? g_h : g_agg;
    float* op;
    if (SEL == 0) op = g_qkv; else op = outparam;

    __shared__ float sA[128][36];
    __shared__ float sB[32][132];
    int bm = blockIdx.x, bn = blockIdx.y;
    int tid = threadIdx.x;
    int warp = tid >> 5, lane = tid & 31;
    int wm = warp & 3;          // m offset wm*32
    int wn = warp >> 2;         // n offset wn*64
    int lr = lane >> 2;         // groupID 0..7
    int lc = lane & 3;          // threadID_in_group 0..3

    float acc[2][8][4];
    #pragma unroll
    for (int t = 0; t < 2; t++)
        #pragma unroll
        for (int n = 0; n < 8; n++)
            #pragma unroll
            for (int j = 0; j < 4; j++) acc[t][n][j] = 0.f;

    for (int k0 = 0; k0 < D_MODEL; k0 += 32) {
        #pragma unroll
        for (int i = tid; i < 128 * 8; i += 256) {
            int r = i >> 3, c4 = (i & 7) * 4;
            int gr = min(bm * 128 + r, N_NODES - 1);
            float4 v = *(const float4*)&a_src[gr * D_MODEL + k0 + c4];
            *(float4*)&sA[r][c4] = v;
        }
        #pragma unroll
        for (int i = tid; i < 32 * 32; i += 256) {
            int r = i >> 5, c4 = (i & 31) * 4;
            float4 v = *(const float4*)&w[(k0 + r) * WSTRIDE + bn * 128 + c4];
            *(float4*)&sB[r][c4] = v;
        }
        __syncthreads();
        #pragma unroll
        for (int ks = 0; ks < 4; ks++) {
            int kk = ks * 8;
            // A fragments: hi/lo split for 3xTF32
            unsigned ah[2][4], al[2][4];
            #pragma unroll
            for (int t = 0; t < 2; t++) {
                int r0 = wm * 32 + t * 16 + lr;
                float f0 = sA[r0][kk + lc];
                float f1 = sA[r0 + 8][kk + lc];
                float f2 = sA[r0][kk + lc + 4];
                float f3 = sA[r0 + 8][kk + lc + 4];
                ah[t][0] = f2tf32(f0); al[t][0] = f2tf32(f0 - __uint_as_float(ah[t][0]));
                ah[t][1] = f2tf32(f1); al[t][1] = f2tf32(f1 - __uint_as_float(ah[t][1]));
                ah[t][2] = f2tf32(f2); al[t][2] = f2tf32(f2 - __uint_as_float(ah[t][2]));
                ah[t][3] = f2tf32(f3); al[t][3] = f2tf32(f3 - __uint_as_float(ah[t][3]));
            }
            #pragma unroll
            for (int n = 0; n < 8; n++) {
                int c = wn * 64 + n * 8 + lr;
                float g0 = sB[kk + lc][c];
                float g1 = sB[kk + lc + 4][c];
                unsigned bh[2], bl[2];
                bh[0] = f2tf32(g0); bl[0] = f2tf32(g0 - __uint_as_float(bh[0]));
                bh[1] = f2tf32(g1); bl[1] = f2tf32(g1 - __uint_as_float(bh[1]));
                #pragma unroll
                for (int t = 0; t < 2; t++) {
                    mma_tf32(acc[t][n], al[t], bh);   // lo*hi
                    mma_tf32(acc[t][n], ah[t], bl);   // hi*lo
                    mma_tf32(acc[t][n], ah[t], bh);   // hi*hi
                }
            }
        }
        __syncthreads();
    }

    // epilogue
    #pragma unroll
    for (int t = 0; t < 2; t++) {
        #pragma unroll
        for (int n = 0; n < 8; n++) {
            int c = bn * 128 + wn * 64 + n * 8 + 2 * lc;
            float b0 = b[c], b1 = b[c + 1];
            #pragma unroll
            for (int half = 0; half < 2; half++) {
                int node = bm * 128 + wm * 32 + t * 16 + lr + half * 8;
                if (node < N_NODES) {
                    float v0 = acc[t][n][half * 2]     + b0;
                    float v1 = acc[t][n][half * 2 + 1] + b1;
                    if (SEL == 1) {
                        v0 += x[node * D_MODEL + c];
                        v1 += x[node * D_MODEL + c + 1];
                    }
                    op[node * OSTRIDE + c]     = v0;
                    op[node * OSTRIDE + c + 1] = v1;
                }
            }
        }
    }
}

// ---------------- fused edge phase: online softmax, single pass -------------
__global__ void k_edge_fused(const float* __restrict__ ea) {
    int node = (blockIdx.x * blockDim.x + threadIdx.x) >> 5;
    if (node >= N_NODES) return;
    int lane = threadIdx.x & 31;
    int beg = g_off[node], end = g_off[node + 1];

    float4 q4 = *(const float4*)&g_qkv[node * 384 + lane * 4];

    float m = -CUDART_INF_F, S = 0.f;
    float ax = 0.f, ay = 0.f, az = 0.f, aw = 0.f;
    for (int e = beg; e < end; e++) {
        int src = g_csr_src[e];
        int eid = g_csr_eid[e];
        float4 vv = *(const float4*)&g_qkv[src * 384 + 256 + lane * 4];
        float4 kv = *(const float4*)&g_qkv[src * 384 + 128 + lane * 4];
        float4 av = *(const float4*)&ea[(size_t)eid * D_MODEL + lane * 4];
        float p = q4.x * (kv.x + av.x) + q4.y * (kv.y + av.y)
                + q4.z * (kv.z + av.z) + q4.w * (kv.w + av.w);
        p += __shfl_xor_sync(0xFFFFFFFFu, p, 1);
        p += __shfl_xor_sync(0xFFFFFFFFu, p, 2);   // 4-lane head group shares sum
        p *= 0.25f;                                 // DH^-0.5
        float mn = fmaxf(m, p);
        float sc = __expf(m - mn);                  // first iter: exp(-inf)=0
        float ex = __expf(p - mn);
        S  = S * sc + ex;
        ax = ax * sc + ex * vv.x;
        ay = ay * sc + ex * vv.y;
        az = az * sc + ex * vv.z;
        aw = aw * sc + ex * vv.w;
        m = mn;
    }
    float r = 1.f / fmaxf(S, 1e-16f);
    float4 o; o.x = ax * r; o.y = ay * r; o.z = az * r; o.w = aw * r;
    if (beg == end) { o.x = 0.f; o.y = 0.f; o.z = 0.f; o.w = 0.f; }
    *(float4*)&g_agg[node * D_MODEL + lane * 4] = o;
}

// ---------------- launch -----------------------------------------------------
extern "C" void kernel_launch(void* const* d_in, const int* in_sizes, int n_in,
                              void* d_out, int out_size) {
    const float* x     = (const float*)d_in[0];
    const float* ea    = (const float*)d_in[1];
    const float* qkv_w = (const float*)d_in[2];
    const float* qkv_b = (const float*)d_in[3];
    const float* out_w = (const float*)d_in[4];
    const float* out_b = (const float*)d_in[5];
    const float* ln_g  = (const float*)d_in[6];
    const float* ln_b  = (const float*)d_in[7];
    const int*   ei    = (const int*)d_in[8];   // int32 [2, E]
    float* out = (float*)d_out;

    // CSR build
    k_zero_cnt<<<(N_NODES + 255) / 256, 256>>>();
    k_hist<<<(N_EDGES + 255) / 256, 256>>>(ei);
    k_scan<<<1, 1024>>>();
    k_scatter<<<(N_EDGES + 255) / 256, 256>>>(ei);

    // layernorm
    k_ln<<<(N_NODES + 7) / 8, 256>>>(x, ln_g, ln_b);

    // qkv gemm: 3xTF32 tensor cores
    {
        dim3 g((N_NODES + 127) / 128, 3);
        k_gemm_tc<0><<<g, 256>>>(qkv_w, qkv_b, nullptr, nullptr);
    }

    // fused edge phase
    k_edge_fused<<<(N_NODES + 7) / 8, 256>>>(ea);

    // out gemm + bias + residual
    {
        dim3 g((N_NODES + 127) / 128, 1);
        k_gemm_tc<1><<<g, 256>>>(out_w, out_b, x, out);
    }
}